// round 15
// baseline (speedup 1.0000x reference)
#include <cuda_runtime.h>
#include <cstdint>

// Neural CDE, B=128, T=1024, D=32, H=64, W=128.
// Streaming design v3 (R14 + iW0-stride fix): 64 persistent CTAs x 1024
// threads (32 warps, occ 50%), 2 batches/CTA. vW2 (2112x128 fp32, 1.08MB)
// streamed from L2 each step (per-SM L1 wavefront floor = 8.4K cyc).
// dx precomputed into a __device__ buffer (kills a phase+sync per step),
// phase4(t-1) merged into phase2(t) (shares v loads), bias+tanh.approx
// folded into layer 3, all phases use all 1024 threads via 4-way k-splits.

namespace {

constexpr int Bn = 128;
constexpr int Tn = 1024;
constexpr int Dn = 32;
constexpr int Hn = 64;
constexpr int Wn = 128;
constexpr int Cn = Dn + 1;      // 33
constexpr int On = Hn * Cn;     // 2112
constexpr int NB = 2;
constexpr int NCTA = 64;
constexpr int NT = 1024;        // 32 warps

using u64 = unsigned long long;

struct __align__(16) Smem {
  float vW0[Wn * 68];    // padded rows (col0 = t coeff, cols 65..67 zero)
  float vW1[Wn * 132];   // padded rows
  float vb0[Wn];
  float vb1[Wn];
  float vb2[On];
  float z1[NB * 132];
  float z2[NB * 132];
  float inp[NB * 68];    // [t, yhat(64), 0,0,0]
  float v[NB * On];      // vector field values
  float yst[NB * Hn];    // readout staging
};

__device__ float g_dx[Bn][Tn][Cn];   // dx[b][t][c], t>=1 (t=0 row stays 0)

__device__ __forceinline__ float lipswish(float x) {
  float e = __expf(-x);
  return __fdividef(0.909f * x, 1.0f + e);
}
__device__ __forceinline__ float tanha(float x) {
  float r;
  asm("tanh.approx.f32 %0, %1;" : "=f"(r) : "f"(x));
  return r;
}
__device__ __forceinline__ float dot4(float4 a, float4 b, float acc) {
  acc = fmaf(a.x, b.x, acc);
  acc = fmaf(a.y, b.y, acc);
  acc = fmaf(a.z, b.z, acc);
  acc = fmaf(a.w, b.w, acc);
  return acc;
}
__device__ __forceinline__ void ffma2(u64& acc, u64 a, u64 b) {
  asm("fma.rn.f32x2 %0, %1, %2, %0;" : "+l"(acc) : "l"(a), "l"(b));
}
__device__ __forceinline__ float hadd2(u64 a) {
  float lo, hi;
  asm("mov.b64 {%0, %1}, %2;" : "=f"(lo), "=f"(hi) : "l"(a));
  return lo + hi;
}

// ---- the three vf layers; sm.inp must hold [t, yhat, 0..]; writes sm.v ----
// Starts after a sync (inp ready); ends with __syncthreads (v visible).
__device__ __forceinline__ void vf_layers(Smem& sm, const float* __restrict__ vW2) {
  const int tid = threadIdx.x;
  const int w = tid >> 3;           // 0..127
  const int nb = (tid >> 2) & 1;
  const int ks = tid & 3;

  // ---- layer 1: z1 = lipswish(vW0 @ inp + vb0); 4-way k-split ----
  {
    float a = 0.f;
    const float4* wr = reinterpret_cast<const float4*>(&sm.vW0[w * 68]);
    const float4* ir = reinterpret_cast<const float4*>(&sm.inp[nb * 68]);
#pragma unroll
    for (int j = ks; j < 17; j += 4) a = dot4(wr[j], ir[j], a);
    a += __shfl_xor_sync(0xffffffffu, a, 1);
    a += __shfl_xor_sync(0xffffffffu, a, 2);
    if (ks == 0) sm.z1[nb * 132 + w] = lipswish(a + sm.vb0[w]);
  }
  __syncthreads();

  // ---- layer 2: z2 = lipswish(vW1 @ z1 + vb1); 4-way k-split ----
  {
    float a = 0.f;
    const float4* wr = reinterpret_cast<const float4*>(&sm.vW1[w * 132]);
    const float4* zr = reinterpret_cast<const float4*>(&sm.z1[nb * 132]);
#pragma unroll
    for (int j = ks; j < 32; j += 4) a = dot4(wr[j], zr[j], a);
    a += __shfl_xor_sync(0xffffffffu, a, 1);
    a += __shfl_xor_sync(0xffffffffu, a, 2);
    if (ks == 0) sm.z2[nb * 132 + w] = lipswish(a + sm.vb1[w]);
  }
  __syncthreads();

  // ---- layer 3: v = tanh(vW2 @ z2 + vb2), streamed from L2 ----
  // 8 lanes per row (kl), 4 rows per body (sub); LDG.128 = 4 lines minimum.
  {
    const int wid = tid >> 5;       // 0..31
    const int lane = tid & 31;
    const int sub = lane >> 3;
    const int kl = lane & 7;

    ulonglong2 zc0[4], zc1[4];
#pragma unroll
    for (int j = 0; j < 4; ++j) {
      zc0[j] = *reinterpret_cast<const ulonglong2*>(&sm.z2[kl * 4 + j * 32]);
      zc1[j] = *reinterpret_cast<const ulonglong2*>(&sm.z2[132 + kl * 4 + j * 32]);
    }

    // warps 0-15: 17 bodies (68 rows); warps 16-31: 16 bodies (64 rows)
    const int nbody = (wid < 16) ? 17 : 16;
    const int rbase = (wid < 16) ? wid * 68 : 1088 + (wid - 16) * 64;
    const float* lane_base = vW2 + (size_t)(rbase + sub) * Wn + kl * 4;

    ulonglong2 wA[4], wB[4];
    auto loadb = [&](ulonglong2* wv, int i) {
      const float* p = lane_base + (size_t)i * 512;
#pragma unroll
      for (int j = 0; j < 4; ++j)
        wv[j] = *reinterpret_cast<const ulonglong2*>(p + j * 32);
    };
    auto body = [&](const ulonglong2* wv, int i) {
      u64 a0 = 0ull, a1 = 0ull;
#pragma unroll
      for (int j = 0; j < 4; ++j) {
        ffma2(a0, wv[j].x, zc0[j].x); ffma2(a0, wv[j].y, zc0[j].y);
        ffma2(a1, wv[j].x, zc1[j].x); ffma2(a1, wv[j].y, zc1[j].y);
      }
      float s0 = hadd2(a0), s1 = hadd2(a1);
#pragma unroll
      for (int m = 1; m < 8; m <<= 1) {
        s0 += __shfl_xor_sync(0xffffffffu, s0, m);
        s1 += __shfl_xor_sync(0xffffffffu, s1, m);
      }
      if (kl == 0) {
        const int row = rbase + 4 * i + sub;
        const float bias = sm.vb2[row];
        sm.v[row] = tanha(s0 + bias);
        sm.v[On + row] = tanha(s1 + bias);
      }
    };

    loadb(wA, 0);
    int i = 0;
#pragma unroll 1
    for (; i + 2 <= nbody; i += 2) {
      loadb(wB, i + 1);
      body(wA, i);
      if (i + 2 < nbody) loadb(wA, i + 2);
      body(wB, i + 1);
    }
    if (i < nbody) body(wA, i);
  }
  __syncthreads();
}

__global__ void prep_dx_kernel(const float* __restrict__ ts,
                               const float* __restrict__ ys) {
  const int total = Bn * (Tn - 1) * Cn;
  for (int i = blockIdx.x * blockDim.x + threadIdx.x; i < total;
       i += gridDim.x * blockDim.x) {
    const int c = i % Cn;
    const int r = i / Cn;
    const int t = r % (Tn - 1) + 1;
    const int b = r / (Tn - 1);
    float d;
    if (c == 0) {
      d = ts[t] - ts[t - 1];
    } else {
      const size_t base = ((size_t)b * Tn) * Dn + (c - 1);
      d = ys[base + (size_t)t * Dn] - ys[base + (size_t)(t - 1) * Dn];
    }
    g_dx[b][t][c] = d;
  }
}

__global__ void __launch_bounds__(NT, 1)
ncde_kernel(const float* __restrict__ ts, const float* __restrict__ ys,
            const float* __restrict__ iW0, const float* __restrict__ ib0,
            const float* __restrict__ iW1, const float* __restrict__ ib1,
            const float* __restrict__ iW2, const float* __restrict__ ib2,
            const float* __restrict__ vW0, const float* __restrict__ vb0,
            const float* __restrict__ vW1, const float* __restrict__ vb1,
            const float* __restrict__ vW2, const float* __restrict__ vb2,
            const float* __restrict__ rW, const float* __restrict__ rb,
            float* __restrict__ out) {
  extern __shared__ char smem_raw[];
  Smem& sm = *reinterpret_cast<Smem*>(smem_raw);
  const int tid = threadIdx.x;
  const int b0 = blockIdx.x * NB;

  // ---- load small weights into SMEM ----
  for (int i = tid; i < Wn * 68; i += NT) {
    const int r = i / 68, c = i - r * 68;
    sm.vW0[i] = (c < 65) ? vW0[r * 65 + c] : 0.0f;
  }
  for (int i = tid; i < Wn * Wn; i += NT)
    sm.vW1[(i >> 7) * 132 + (i & 127)] = vW1[i];
  if (tid < Wn) { sm.vb0[tid] = vb0[tid]; sm.vb1[tid] = vb1[tid]; }
  for (int i = tid; i < On; i += NT) sm.vb2[i] = vb2[i];
  if (tid < NB * 3) sm.inp[(tid / 3) * 68 + 65 + (tid % 3)] = 0.0f;  // pads
  __syncthreads();

  // ---- initial MLP (tid < 256: w = tid&127, nb = tid>>7) ----
  // NOTE: iW0 has in_f = D+1 = 33 (stride 33), unlike vW0's 65.
  {
    const int wi = tid & 127, nbi = tid >> 7;
    if (tid < 256) {
      const int b = b0 + nbi;
      float a = ib0[wi] + iW0[wi * Cn] * ts[0];
      for (int c = 0; c < Dn; ++c)
        a = fmaf(iW0[wi * Cn + 1 + c], ys[((size_t)b * Tn) * Dn + c], a);
      sm.z1[nbi * 132 + wi] = fmaxf(a, 0.0f);
    }
    __syncthreads();
    if (tid < 256) {
      float a = ib1[wi];
      for (int k = 0; k < Wn; ++k)
        a = fmaf(iW1[wi * Wn + k], sm.z1[nbi * 132 + k], a);
      sm.z2[nbi * 132 + wi] = fmaxf(a, 0.0f);
    }
    __syncthreads();
  }

  // ---- per-thread recurrence state on tid<512, ks==0 threads ----
  // mapping: nb_s = tid>>8, h_s = (tid>>2)&63, ks_s = tid&3
  const int nb_s = tid >> 8;
  const int h_s = (tid >> 2) & 63;
  const int ks_s = tid & 3;
  float y_r = 0.f, yhat_r = 0.f, s_old_r = 0.f;
  if (tid < 512 && ks_s == 0) {
    float a = ib2[h_s];
    for (int k = 0; k < Wn; ++k)
      a = fmaf(iW2[h_s * Wn + k], sm.z2[nb_s * 132 + k], a);
    y_r = a;
    yhat_r = a;
    sm.inp[nb_s * 68 + 1 + h_s] = a;
    if (h_s == 0) sm.inp[nb_s * 68] = ts[0];
  }
  __syncthreads();

  vf_layers(sm, vW2);  // v0 = vf(ts[0], y0)

  // ---- main scan over 1023 steps ----
#pragma unroll 1
  for (int t = 1; t < Tn; ++t) {
    // merged state phase (tid < 512):
    //   phase4(t-1): y += 0.5*(s_old + v.dx[t-1])   [skipped at t==1]
    //   phase2(t):   s = v.dx[t]; yhat <- 2y - yhat + s; publish inp
    if (tid < 512) {
      const float* vr = &sm.v[nb_s * On + h_s * Cn];
      const float* dxc = &g_dx[b0 + nb_s][t][0];
      const float* dxp = &g_dx[b0 + nb_s][t - 1][0];
      float sc = 0.f, sp = 0.f;
#pragma unroll
      for (int j = 0; j < 9; ++j) {
        const int c = ks_s + 4 * j;
        if (c < Cn) {
          const float vv = vr[c];
          sc = fmaf(vv, dxc[c], sc);
          sp = fmaf(vv, dxp[c], sp);
        }
      }
      sc += __shfl_xor_sync(0xffffffffu, sc, 1);
      sc += __shfl_xor_sync(0xffffffffu, sc, 2);
      sp += __shfl_xor_sync(0xffffffffu, sp, 1);
      sp += __shfl_xor_sync(0xffffffffu, sp, 2);
      if (ks_s == 0) {
        if (t > 1) y_r += 0.5f * (s_old_r + sp);
        const float yh = 2.0f * y_r - yhat_r + sc;
        yhat_r = yh;
        s_old_r = sc;
        sm.inp[nb_s * 68 + 1 + h_s] = yh;
        if (h_s == 0) sm.inp[nb_s * 68] = ts[t];
      }
    }
    __syncthreads();

    vf_layers(sm, vW2);  // v <- vf(ts[t], yhat)
  }

  // ---- trailing phase4 for t = 1023 ----
  if (tid < 512) {
    const float* vr = &sm.v[nb_s * On + h_s * Cn];
    const float* dxc = &g_dx[b0 + nb_s][Tn - 1][0];
    float sc = 0.f;
#pragma unroll
    for (int j = 0; j < 9; ++j) {
      const int c = ks_s + 4 * j;
      if (c < Cn) sc = fmaf(vr[c], dxc[c], sc);
    }
    sc += __shfl_xor_sync(0xffffffffu, sc, 1);
    sc += __shfl_xor_sync(0xffffffffu, sc, 2);
    if (ks_s == 0) {
      y_r += 0.5f * (s_old_r + sc);
      sm.yst[nb_s * Hn + h_s] = y_r;
    }
  }
  __syncthreads();

  // ---- readout: out[b] = y[b].rW + rb ----
  if (tid < NB) {
    float a = rb[0];
    for (int h = 0; h < Hn; ++h) a = fmaf(sm.yst[tid * Hn + h], rW[h], a);
    out[b0 + tid] = a;
  }
}

}  // namespace

extern "C" void kernel_launch(void* const* d_in, const int* in_sizes, int n_in,
                              void* d_out, int out_size) {
  const float* ts  = (const float*)d_in[0];
  const float* ys  = (const float*)d_in[1];
  const float* iW0 = (const float*)d_in[2];
  const float* ib0 = (const float*)d_in[3];
  const float* iW1 = (const float*)d_in[4];
  const float* ib1 = (const float*)d_in[5];
  const float* iW2 = (const float*)d_in[6];
  const float* ib2 = (const float*)d_in[7];
  const float* vW0 = (const float*)d_in[8];
  const float* vb0 = (const float*)d_in[9];
  const float* vW1 = (const float*)d_in[10];
  const float* vb1 = (const float*)d_in[11];
  const float* vW2 = (const float*)d_in[12];
  const float* vb2 = (const float*)d_in[13];
  const float* rW  = (const float*)d_in[14];
  const float* rb  = (const float*)d_in[15];
  float* out = (float*)d_out;

  prep_dx_kernel<<<1056, 256>>>(ts, ys);

  cudaFuncSetAttribute(ncde_kernel, cudaFuncAttributeMaxDynamicSharedMemorySize,
                       (int)sizeof(Smem));
  ncde_kernel<<<NCTA, NT, sizeof(Smem)>>>(ts, ys, iW0, ib0, iW1, ib1, iW2, ib2,
                                          vW0, vb0, vW1, vb1, vW2, vb2, rW, rb,
                                          out);
}

// round 16
// speedup vs baseline: 3.1993x; 3.1993x over previous
#include <cuda_runtime.h>
#include <cstdint>

// Neural CDE, B=128, T=1024, D=32, H=64, W=128.
// Streaming v4 = R15 structure on R8's resource shape:
//   NT=512 (128 regs/thread — R15's NT=1024 capped regs at 64 and SPILLED).
//   dx precomputed (no per-step phase 1), merged phase4(t-1)+phase2(t),
//   bias+tanh.approx folded into layer 3 (no separate pass), and the first
//   two layer-3 weight bodies prefetched BEFORE layers 1-2 (weights depend
//   on nothing; hides lead L2 latency behind the small phases).
// 4 __syncthreads per step. vW2 (1.08MB fp32) streamed from L2 per step.

namespace {

constexpr int Bn = 128;
constexpr int Tn = 1024;
constexpr int Dn = 32;
constexpr int Hn = 64;
constexpr int Wn = 128;
constexpr int Cn = Dn + 1;      // 33
constexpr int On = Hn * Cn;     // 2112
constexpr int NB = 2;
constexpr int NCTA = 64;
constexpr int NT = 512;         // 16 warps, 128 regs/thread available
constexpr int RPW = On / 16;    // 132 rows per warp
constexpr int NBODY = RPW / 4;  // 33 bodies of 4 rows

using u64 = unsigned long long;

struct __align__(16) Smem {
  float vW0[Wn * 68];    // padded rows (col0 = t coeff, cols 65..67 zero)
  float vW1[Wn * 132];   // padded rows
  float vb0[Wn];
  float vb1[Wn];
  float vb2[On];
  float z1[NB * 132];
  float z2[NB * 132];
  float inp[NB * 68];    // [t, yhat(64), 0,0,0]
  float v[NB * On];      // vector field values
  float yst[NB * Hn];    // readout staging
};

__device__ float g_dx[Bn][Tn][Cn];   // dx[b][t][c], t>=1 (t=0 row zero-init)

__device__ __forceinline__ float lipswish(float x) {
  float e = __expf(-x);
  return __fdividef(0.909f * x, 1.0f + e);
}
__device__ __forceinline__ float tanha(float x) {
  float r;
  asm("tanh.approx.f32 %0, %1;" : "=f"(r) : "f"(x));
  return r;
}
__device__ __forceinline__ float dot4(float4 a, float4 b, float acc) {
  acc = fmaf(a.x, b.x, acc);
  acc = fmaf(a.y, b.y, acc);
  acc = fmaf(a.z, b.z, acc);
  acc = fmaf(a.w, b.w, acc);
  return acc;
}
__device__ __forceinline__ void ffma2(u64& acc, u64 a, u64 b) {
  asm("fma.rn.f32x2 %0, %1, %2, %0;" : "+l"(acc) : "l"(a), "l"(b));
}
__device__ __forceinline__ float hadd2(u64 a) {
  float lo, hi;
  asm("mov.b64 {%0, %1}, %2;" : "=f"(lo), "=f"(hi) : "l"(a));
  return lo + hi;
}

// ---- one vf evaluation; sm.inp holds [t, yhat, 0..]; writes sm.v ----
// Caller syncs before entry; ends with __syncthreads (v visible).
__device__ __forceinline__ void vf_eval(Smem& sm, const float* __restrict__ vW2) {
  const int tid = threadIdx.x;
  const int wid = tid >> 5;
  const int lane = tid & 31;
  const int sub = lane >> 3;        // row within a 4-row body
  const int kl = lane & 7;          // 16B k-chunk within the row

  // ---- prefetch first two layer-3 weight bodies (independent of z2) ----
  const int rbase = wid * RPW;
  const float* lane_base = vW2 + (size_t)(rbase + sub) * Wn + kl * 4;
  ulonglong2 wA[4], wB[4], wC[4];
  auto loadb = [&](ulonglong2* wv, int i) {
    const float* p = lane_base + (size_t)i * 512;  // 4 rows * 128 floats
#pragma unroll
    for (int j = 0; j < 4; ++j)
      wv[j] = *reinterpret_cast<const ulonglong2*>(p + j * 32);
  };
  loadb(wA, 0);
  loadb(wB, 1);

  // ---- layer 1: z1 = lipswish(vW0 @ inp + vb0); 256 threads ----
  if (tid < 256) {
    const int nb = tid >> 7, w = tid & 127;
    float a = sm.vb0[w];
    const float4* wr = reinterpret_cast<const float4*>(&sm.vW0[w * 68]);
    const float4* ir = reinterpret_cast<const float4*>(&sm.inp[nb * 68]);
#pragma unroll
    for (int q = 0; q < 17; ++q) a = dot4(wr[q], ir[q], a);
    sm.z1[nb * 132 + w] = lipswish(a);
  }
  __syncthreads();

  // ---- layer 2: z2 = lipswish(vW1 @ z1 + vb1) ----
  if (tid < 256) {
    const int nb = tid >> 7, w = tid & 127;
    float a = sm.vb1[w];
    const float4* wr = reinterpret_cast<const float4*>(&sm.vW1[w * 132]);
    const float4* zr = reinterpret_cast<const float4*>(&sm.z1[nb * 132]);
#pragma unroll
    for (int q = 0; q < 32; ++q) a = dot4(wr[q], zr[q], a);
    sm.z2[nb * 132 + w] = lipswish(a);
  }
  __syncthreads();

  // ---- layer 3: v = tanh(vW2 @ z2 + vb2); streamed, tanh folded ----
  {
    ulonglong2 zc0[4], zc1[4];
#pragma unroll
    for (int j = 0; j < 4; ++j) {
      zc0[j] = *reinterpret_cast<const ulonglong2*>(&sm.z2[kl * 4 + j * 32]);
      zc1[j] = *reinterpret_cast<const ulonglong2*>(&sm.z2[132 + kl * 4 + j * 32]);
    }

    auto body = [&](const ulonglong2* wv, int i) {
      u64 a0 = 0ull, a1 = 0ull;
#pragma unroll
      for (int j = 0; j < 4; ++j) {
        ffma2(a0, wv[j].x, zc0[j].x); ffma2(a0, wv[j].y, zc0[j].y);
        ffma2(a1, wv[j].x, zc1[j].x); ffma2(a1, wv[j].y, zc1[j].y);
      }
      float s0 = hadd2(a0), s1 = hadd2(a1);
#pragma unroll
      for (int m = 1; m < 8; m <<= 1) {
        s0 += __shfl_xor_sync(0xffffffffu, s0, m);
        s1 += __shfl_xor_sync(0xffffffffu, s1, m);
      }
      if (kl == 0) {
        const int row = rbase + 4 * i + sub;
        const float bias = sm.vb2[row];
        sm.v[row] = tanha(s0 + bias);
        sm.v[On + row] = tanha(s1 + bias);
      }
    };

#pragma unroll 1
    for (int i = 0; i < NBODY; i += 3) {  // 33 = 3 * 11, exact
      const int pf2 = (i + 2 < NBODY) ? i + 2 : NBODY - 1;
      const int pf3 = (i + 3 < NBODY) ? i + 3 : NBODY - 1;
      const int pf4 = (i + 4 < NBODY) ? i + 4 : NBODY - 1;
      loadb(wC, pf2);
      body(wA, i);
      loadb(wA, pf3);
      body(wB, i + 1);
      loadb(wB, pf4);
      body(wC, i + 2);
    }
  }
  __syncthreads();
}

__global__ void prep_dx_kernel(const float* __restrict__ ts,
                               const float* __restrict__ ys) {
  const int total = Bn * (Tn - 1) * Cn;
  for (int i = blockIdx.x * blockDim.x + threadIdx.x; i < total;
       i += gridDim.x * blockDim.x) {
    const int c = i % Cn;
    const int r = i / Cn;
    const int t = r % (Tn - 1) + 1;
    const int b = r / (Tn - 1);
    float d;
    if (c == 0) {
      d = ts[t] - ts[t - 1];
    } else {
      const size_t base = ((size_t)b * Tn) * Dn + (c - 1);
      d = ys[base + (size_t)t * Dn] - ys[base + (size_t)(t - 1) * Dn];
    }
    g_dx[b][t][c] = d;
  }
}

__global__ void __launch_bounds__(NT, 1)
ncde_kernel(const float* __restrict__ ts, const float* __restrict__ ys,
            const float* __restrict__ iW0, const float* __restrict__ ib0,
            const float* __restrict__ iW1, const float* __restrict__ ib1,
            const float* __restrict__ iW2, const float* __restrict__ ib2,
            const float* __restrict__ vW0, const float* __restrict__ vb0,
            const float* __restrict__ vW1, const float* __restrict__ vb1,
            const float* __restrict__ vW2, const float* __restrict__ vb2,
            const float* __restrict__ rW, const float* __restrict__ rb,
            float* __restrict__ out) {
  extern __shared__ char smem_raw[];
  Smem& sm = *reinterpret_cast<Smem*>(smem_raw);
  const int tid = threadIdx.x;
  const int b0 = blockIdx.x * NB;

  // ---- load small weights into SMEM ----
  for (int i = tid; i < Wn * 68; i += NT) {
    const int r = i / 68, c = i - r * 68;
    sm.vW0[i] = (c < 65) ? vW0[r * 65 + c] : 0.0f;
  }
  for (int i = tid; i < Wn * Wn; i += NT)
    sm.vW1[(i >> 7) * 132 + (i & 127)] = vW1[i];
  if (tid < Wn) { sm.vb0[tid] = vb0[tid]; sm.vb1[tid] = vb1[tid]; }
  for (int i = tid; i < On; i += NT) sm.vb2[i] = vb2[i];
  if (tid < NB * 3) sm.inp[(tid / 3) * 68 + 65 + (tid % 3)] = 0.0f;  // pads
  __syncthreads();

  // ---- initial MLP (tid < 256; iW0 stride = Cn = 33!) ----
  {
    const int wi = tid & 127, nbi = tid >> 7;
    if (tid < 256) {
      const int b = b0 + nbi;
      float a = ib0[wi] + iW0[wi * Cn] * ts[0];
      for (int c = 0; c < Dn; ++c)
        a = fmaf(iW0[wi * Cn + 1 + c], ys[((size_t)b * Tn) * Dn + c], a);
      sm.z1[nbi * 132 + wi] = fmaxf(a, 0.0f);
    }
    __syncthreads();
    if (tid < 256) {
      float a = ib1[wi];
      for (int k = 0; k < Wn; ++k)
        a = fmaf(iW1[wi * Wn + k], sm.z1[nbi * 132 + k], a);
      sm.z2[nbi * 132 + wi] = fmaxf(a, 0.0f);
    }
    __syncthreads();
  }

  // ---- per-thread recurrence state: tid<512, nb_s = tid>>8,
  //      h_s = (tid>>2)&63, ks_s = tid&3; state lives on ks_s==0 ----
  const int nb_s = tid >> 8;
  const int h_s = (tid >> 2) & 63;
  const int ks_s = tid & 3;
  float y_r = 0.f, yhat_r = 0.f, s_old_r = 0.f;
  if (ks_s == 0) {
    float a = ib2[h_s];
    for (int k = 0; k < Wn; ++k)
      a = fmaf(iW2[h_s * Wn + k], sm.z2[nb_s * 132 + k], a);
    y_r = a;
    yhat_r = a;
    sm.inp[nb_s * 68 + 1 + h_s] = a;
    if (h_s == 0) sm.inp[nb_s * 68] = ts[0];
  }
  __syncthreads();

  vf_eval(sm, vW2);  // v0 = vf(ts[0], y0)

  // ---- main scan over 1023 steps ----
#pragma unroll 1
  for (int t = 1; t < Tn; ++t) {
    // merged state phase:
    //   phase4(t-1): y += 0.5*(s_old + v.dx[t-1])   [skipped at t==1]
    //   phase2(t):   s = v.dx[t]; yhat <- 2y - yhat + s; publish inp
    {
      const float* vr = &sm.v[nb_s * On + h_s * Cn];
      const float* dxc = &g_dx[b0 + nb_s][t][0];
      const float* dxp = &g_dx[b0 + nb_s][t - 1][0];
      float sc = 0.f, sp = 0.f;
#pragma unroll
      for (int j = 0; j < 9; ++j) {
        const int c = ks_s + 4 * j;
        if (c < Cn) {
          const float vv = vr[c];
          sc = fmaf(vv, dxc[c], sc);
          sp = fmaf(vv, dxp[c], sp);
        }
      }
      sc += __shfl_xor_sync(0xffffffffu, sc, 1);
      sc += __shfl_xor_sync(0xffffffffu, sc, 2);
      sp += __shfl_xor_sync(0xffffffffu, sp, 1);
      sp += __shfl_xor_sync(0xffffffffu, sp, 2);
      if (ks_s == 0) {
        if (t > 1) y_r += 0.5f * (s_old_r + sp);
        const float yh = 2.0f * y_r - yhat_r + sc;
        yhat_r = yh;
        s_old_r = sc;
        sm.inp[nb_s * 68 + 1 + h_s] = yh;
        if (h_s == 0) sm.inp[nb_s * 68] = ts[t];
      }
    }
    __syncthreads();

    vf_eval(sm, vW2);  // v <- vf(ts[t], yhat)
  }

  // ---- trailing phase4 for t = 1023 ----
  {
    const float* vr = &sm.v[nb_s * On + h_s * Cn];
    const float* dxc = &g_dx[b0 + nb_s][Tn - 1][0];
    float sc = 0.f;
#pragma unroll
    for (int j = 0; j < 9; ++j) {
      const int c = ks_s + 4 * j;
      if (c < Cn) sc = fmaf(vr[c], dxc[c], sc);
    }
    sc += __shfl_xor_sync(0xffffffffu, sc, 1);
    sc += __shfl_xor_sync(0xffffffffu, sc, 2);
    if (ks_s == 0) {
      y_r += 0.5f * (s_old_r + sc);
      sm.yst[nb_s * Hn + h_s] = y_r;
    }
  }
  __syncthreads();

  // ---- readout: out[b] = y[b].rW + rb ----
  if (tid < NB) {
    float a = rb[0];
    for (int h = 0; h < Hn; ++h) a = fmaf(sm.yst[tid * Hn + h], rW[h], a);
    out[b0 + tid] = a;
  }
}

}  // namespace

extern "C" void kernel_launch(void* const* d_in, const int* in_sizes, int n_in,
                              void* d_out, int out_size) {
  const float* ts  = (const float*)d_in[0];
  const float* ys  = (const float*)d_in[1];
  const float* iW0 = (const float*)d_in[2];
  const float* ib0 = (const float*)d_in[3];
  const float* iW1 = (const float*)d_in[4];
  const float* ib1 = (const float*)d_in[5];
  const float* iW2 = (const float*)d_in[6];
  const float* ib2 = (const float*)d_in[7];
  const float* vW0 = (const float*)d_in[8];
  const float* vb0 = (const float*)d_in[9];
  const float* vW1 = (const float*)d_in[10];
  const float* vb1 = (const float*)d_in[11];
  const float* vW2 = (const float*)d_in[12];
  const float* vb2 = (const float*)d_in[13];
  const float* rW  = (const float*)d_in[14];
  const float* rb  = (const float*)d_in[15];
  float* out = (float*)d_out;

  prep_dx_kernel<<<1056, 256>>>(ts, ys);

  cudaFuncSetAttribute(ncde_kernel, cudaFuncAttributeMaxDynamicSharedMemorySize,
                       (int)sizeof(Smem));
  ncde_kernel<<<NCTA, NT, sizeof(Smem)>>>(ts, ys, iW0, ib0, iW1, ib1, iW2, ib2,
                                          vW0, vb0, vW1, vb1, vW2, vb2, rW, rb,
                                          out);
}